// round 4
// baseline (speedup 1.0000x reference)
#include <cuda_runtime.h>
#include <cuda_bf16.h>

// Masked trapezoid loss:
//   S_b = sum_{j < idx_b} 0.5*(d[j]+d[j+1])*(x[j+1]-x[j]),  d = y_pred - y_true
// rewritten as weighted dot product:
//   S_b = sum_{k=0}^{idx} g_w[k]*d[k] + corr(idx)
// where g_w[k] = 0.5*(x[min(k+1,n-1)] - x[max(k-1,0)]) and
//   corr = -g_w[0]*d[0]                       if idx == 0
//   corr = -0.5*(x[idx+1]-x[idx])*d[idx]      if 1 <= idx <= n-2
//   corr = 0                                  if idx == n-1
// Output: mean_b (S_b)^2, one fp32 scalar.

#define NMAX 8192

__device__ double g_acc;         // batch accumulator (fp64)
__device__ float  g_w[NMAX];     // precomputed trapezoid weights

__global__ void weights_kernel(const float* __restrict__ x, int n) {
    int k = blockIdx.x * blockDim.x + threadIdx.x;
    if (k == 0) g_acc = 0.0;     // reset accumulator each launch (deterministic)
    if (k >= n) return;
    float lo = (k == 0)     ? x[0]     : x[k - 1];
    float hi = (k == n - 1) ? x[n - 1] : x[k + 1];
    g_w[k] = 0.5f * (hi - lo);
}

__global__ __launch_bounds__(256) void row_kernel(
    const float* __restrict__ yp, const float* __restrict__ yt,
    const float* __restrict__ x,  const int* __restrict__ fidx, int n)
{
    __shared__ float warp_sums[8];

    int b = blockIdx.x;
    int idx = fidx[b];
    idx = idx < 0 ? 0 : (idx > n - 1 ? n - 1 : idx);   // clamp as in reference

    const float* yprow = yp + (size_t)b * (size_t)n;
    const float* ytrow = yt + (size_t)b * (size_t)n;
    const float4* p4 = (const float4*)yprow;
    const float4* t4 = (const float4*)ytrow;
    const float4* w4 = (const float4*)g_w;

    // elements 0..idx inclusive -> ceil((idx+1)/4) float4 vectors (n % 4 == 0,
    // so the tail vector stays inside the row; masked lanes contribute 0).
    int nvec = (idx + 4) >> 2;

    float acc = 0.0f;
    for (int v = threadIdx.x; v < nvec; v += blockDim.x) {
        float4 p = p4[v];
        float4 t = t4[v];
        float4 w = w4[v];
        int k = v << 2;
        float d0 = p.x - t.x;
        float d1 = p.y - t.y;
        float d2 = p.z - t.z;
        float d3 = p.w - t.w;
        acc += (k     <= idx) ? w.x * d0 : 0.0f;
        acc += (k + 1 <= idx) ? w.y * d1 : 0.0f;
        acc += (k + 2 <= idx) ? w.z * d2 : 0.0f;
        acc += (k + 3 <= idx) ? w.w * d3 : 0.0f;
    }

    // warp tree reduce
    #pragma unroll
    for (int o = 16; o > 0; o >>= 1)
        acc += __shfl_xor_sync(0xffffffffu, acc, o);

    int lane = threadIdx.x & 31;
    int wid  = threadIdx.x >> 5;
    if (lane == 0) warp_sums[wid] = acc;
    __syncthreads();

    if (wid == 0) {
        acc = (lane < 8) ? warp_sums[lane] : 0.0f;
        #pragma unroll
        for (int o = 4; o > 0; o >>= 1)
            acc += __shfl_xor_sync(0xffffffffu, acc, o);

        if (lane == 0) {
            float dend = yprow[idx] - ytrow[idx];
            float corr;
            if (idx == 0)          corr = -g_w[0] * dend;
            else if (idx < n - 1)  corr = -0.5f * (x[idx + 1] - x[idx]) * dend;
            else                   corr = 0.0f;
            float S = acc + corr;
            atomicAdd(&g_acc, (double)S * (double)S);
        }
    }
}

__global__ void final_kernel(float* __restrict__ out, float invB) {
    out[0] = (float)(g_acc * (double)invB);
}

extern "C" void kernel_launch(void* const* d_in, const int* in_sizes, int n_in,
                              void* d_out, int out_size) {
    // metadata order: y_pred [B*N] f32, y_true [B*N] f32, x_values [N] f32,
    //                 fracture_idx [B] i32
    const float* yp   = (const float*)d_in[0];
    const float* yt   = (const float*)d_in[1];
    const float* x    = (const float*)d_in[2];
    const int*   fidx = (const int*)d_in[3];
    int n = in_sizes[2];
    int B = in_sizes[3];

    weights_kernel<<<(n + 255) / 256, 256>>>(x, n);
    row_kernel<<<B, 256>>>(yp, yt, x, fidx, n);
    final_kernel<<<1, 1>>>((float*)d_out, 1.0f / (float)B);
}